// round 9
// baseline (speedup 1.0000x reference)
#include <cuda_runtime.h>
#include <cuda_bf16.h>
#include <cstdint>

#define NN    8192
#define FIN   256
#define FOUT  128
#define SLOPE 0.01f
#define BM    32             // rows per attn CTA
#define BK    64             // j-tile
#define NJ    (NN / BK)      // 128 tiles

// ---------------- device scratch ----------------
// Wh packed as m16n8k16 B-fragments, LDS.128-friendly:
// u32 idx = K16*1024 + ((wn*4 + nbp)*32 + lane)*4 + nbl*2 + sel
//   (wn = n/64, nbp = (n/16)%4, nbl = (n/8)%2, lane = (n%8)*4 + (k%16)/2%4,
//    sel = (k%16)/8; value = bf16x2(Wh[k][n], Wh[k+1][n]), k even)
__device__ uint32_t g_WhF[NN * 64];
__device__ float g_src[NN], g_dst[NN];
__device__ float g_A[NN], g_C[NN];   // row factors: exp(s-m), exp(.01 s - m)
__device__ float g_B[NN], g_D[NN];   // col factors: exp(d),   exp(.01 d)
__device__ float g_dstmax;

__device__ __forceinline__ uint32_t pack_bf16x2(float lo, float hi) {
    __nv_bfloat162 h2 = __floats2bfloat162_rn(lo, hi);
    return *reinterpret_cast<uint32_t*>(&h2);
}
__device__ __forceinline__ void mma16816(float* d, uint32_t a0, uint32_t a1,
                                         uint32_t a2, uint32_t a3,
                                         uint32_t b0, uint32_t b1) {
    asm volatile(
        "mma.sync.aligned.m16n8k16.row.col.f32.bf16.bf16.f32 "
        "{%0,%1,%2,%3}, {%4,%5,%6,%7}, {%8,%9}, {%0,%1,%2,%3};"
        : "+f"(d[0]), "+f"(d[1]), "+f"(d[2]), "+f"(d[3])
        : "r"(a0), "r"(a1), "r"(a2), "r"(a3), "r"(b0), "r"(b1));
}

// ---------------------------------------------------------------------------
// Kernel A: Wh = h @ W; emits g_WhF (fragment-packed bf16) + g_src/g_dst.
// ---------------------------------------------------------------------------
__global__ __launch_bounds__(256) void wh_kernel(const float* __restrict__ h,
                                                 const float* __restrict__ W,
                                                 const float* __restrict__ a) {
    __shared__ float h_s[64][33];
    __shared__ float W_s[32][FOUT];
    __shared__ float a_s[2 * FOUT];
    __shared__ uint32_t frag_s[4096];   // 16 KB fragment staging

    const int t  = threadIdx.x;
    const int i0 = blockIdx.x * 64;
    a_s[t] = a[t];

    float C[4][8];
#pragma unroll
    for (int r = 0; r < 4; r++)
#pragma unroll
        for (int c = 0; c < 8; c++) C[r][c] = 0.f;

    const int tr = t >> 4, tc = t & 15;

    for (int k0 = 0; k0 < FIN; k0 += 32) {
        {
            int row = t >> 2, colb = (t & 3) * 8;
            const float4* s4 =
                reinterpret_cast<const float4*>(h + (size_t)(i0 + row) * FIN + k0 + colb);
#pragma unroll
            for (int q = 0; q < 2; q++) {
                float4 v = s4[q];
                h_s[row][colb + 4 * q + 0] = v.x;
                h_s[row][colb + 4 * q + 1] = v.y;
                h_s[row][colb + 4 * q + 2] = v.z;
                h_s[row][colb + 4 * q + 3] = v.w;
            }
        }
        {
            int row = t >> 3, colb = (t & 7) * 16;
            const float4* s4 =
                reinterpret_cast<const float4*>(W + (size_t)(k0 + row) * FOUT + colb);
            float4* d4 = reinterpret_cast<float4*>(&W_s[row][colb]);
#pragma unroll
            for (int q = 0; q < 4; q++) d4[q] = s4[q];
        }
        __syncthreads();
#pragma unroll
        for (int kk = 0; kk < 32; kk++) {
            float av[4];
#pragma unroll
            for (int r = 0; r < 4; r++) av[r] = h_s[tr * 4 + r][kk];
            float4 b0 = *reinterpret_cast<const float4*>(&W_s[kk][tc * 8]);
            float4 b1 = *reinterpret_cast<const float4*>(&W_s[kk][tc * 8 + 4]);
            float bv[8] = {b0.x, b0.y, b0.z, b0.w, b1.x, b1.y, b1.z, b1.w};
#pragma unroll
            for (int r = 0; r < 4; r++)
#pragma unroll
                for (int c = 0; c < 8; c++) C[r][c] += av[r] * bv[c];
        }
        __syncthreads();
    }

    float sp[4], dp[4];
#pragma unroll
    for (int r = 0; r < 4; r++) { sp[r] = 0.f; dp[r] = 0.f; }
#pragma unroll
    for (int r = 0; r < 4; r++)
#pragma unroll
        for (int c = 0; c < 8; c++) {
            int col = tc * 8 + c;
            sp[r] += C[r][c] * a_s[col];
            dp[r] += C[r][c] * a_s[FOUT + col];
        }
#pragma unroll
    for (int off = 8; off >= 1; off >>= 1) {
#pragma unroll
        for (int r = 0; r < 4; r++) {
            sp[r] += __shfl_down_sync(0xffffffffu, sp[r], off, 16);
            dp[r] += __shfl_down_sync(0xffffffffu, dp[r], off, 16);
        }
    }
    if (tc == 0) {
#pragma unroll
        for (int r = 0; r < 4; r++) {
            g_src[i0 + tr * 4 + r] = sp[r];
            g_dst[i0 + tr * 4 + r] = dp[r];
        }
    }

    // pack into LDS.128-friendly B-fragment layout
    const int wnp = tc >> 3;          // n/64
    const int nb  = tc & 7;           // (n/8)%8
    const int nbp = nb >> 1, nbl = nb & 1;
#pragma unroll
    for (int q = 0; q < 2; q++) {
        int kk   = tr * 4 + 2 * q;
        int Kloc = kk >> 4;
        int klo  = kk & 15;
        int sel  = klo >> 3;
        int tig  = (klo >> 1) & 3;
#pragma unroll
        for (int c = 0; c < 8; c++) {
            uint32_t v    = pack_bf16x2(C[2 * q][c], C[2 * q + 1][c]);
            int      lane = c * 4 + tig;
            frag_s[Kloc * 1024 + ((wnp * 4 + nbp) * 32 + lane) * 4 + nbl * 2 + sel] = v;
        }
    }
    __syncthreads();
    {
        uint4*       dst = reinterpret_cast<uint4*>(g_WhF + (size_t)i0 * 64);
        const uint4* src = reinterpret_cast<const uint4*>(frag_s);
#pragma unroll
        for (int i = 0; i < 4; i++) dst[t * 4 + i] = src[t * 4 + i];
    }
}

// ---------------------------------------------------------------------------
__global__ __launch_bounds__(256) void dstmax_kernel() {
    __shared__ float red[256];
    int t = threadIdx.x;
    float m = -1e30f;
    for (int i = t; i < NN; i += 256) m = fmaxf(m, g_dst[i]);
    red[t] = m;
    __syncthreads();
    for (int s = 128; s > 0; s >>= 1) {
        if (t < s) red[t] = fmaxf(red[t], red[t + s]);
        __syncthreads();
    }
    if (t == 0) g_dstmax = red[0];
}

__global__ __launch_bounds__(256) void vec_kernel() {
    int   i = blockIdx.x * 256 + threadIdx.x;
    float s = g_src[i], d = g_dst[i];
    float x = s + g_dstmax;
    float m = x > 0.f ? x : SLOPE * x;
    g_A[i] = __expf(s - m);
    g_C[i] = __expf(SLOPE * s - m);
    g_B[i] = __expf(d);
    g_D[i] = __expf(SLOPE * d);
}

// ---------------------------------------------------------------------------
// Kernel D: fused masked softmax + (att @ Wh), bf16 HMMA.
// 256 CTAs x 256 thr (8 warps), 2 CTAs/SM. Warp w: wm=w&1 (16 rows),
// wn=(w>>1)&1 (64 cols), sh=w>>2 (2 of 4 k16-steps).
// Double-buffered whf/vec staging -> ONE sync/tile; adj direct from gmem.
// ---------------------------------------------------------------------------
__global__ __launch_bounds__(256, 2) void attn_kernel(const int* __restrict__ adj,
                                                      float* __restrict__ out) {
    __shared__ __align__(16) uint32_t whf_s[2][4096];   // 32 KB
    __shared__ __align__(16) float dst_s[2][64], bf_s[2][64], df_s[2][64];
    __shared__ __align__(16) float l_red[2 * 128];
    __shared__ float l_s[BM];

    float* red_s = reinterpret_cast<float*>(whf_s);     // post-loop alias (16 KB)

    const int t  = threadIdx.x;
    const int l  = t & 31;
    const int w  = t >> 5;
    const int wm = w & 1;
    const int wn = (w >> 1) & 1;
    const int sh = w >> 2;
    const int i0 = blockIdx.x * BM;

    const int r0  = wm * 16 + (l >> 2);
    const int r1  = r0 + 8;
    const int tig = l & 3;

    const float s0 = g_src[i0 + r0], A0 = g_A[i0 + r0], C0 = g_C[i0 + r0];
    const float s1 = g_src[i0 + r1], A1 = g_A[i0 + r1], C1 = g_C[i0 + r1];

    const uint32_t ones_b = (l < 4) ? 0x3F803F80u : 0u;

    float acc[8][4];
#pragma unroll
    for (int nb = 0; nb < 8; nb++)
#pragma unroll
        for (int q = 0; q < 4; q++) acc[nb][q] = 0.f;
    float lacc[4] = {0.f, 0.f, 0.f, 0.f};

    const uint4* wf_g = reinterpret_cast<const uint4*>(g_WhF);
    const int*   ar0  = adj + (size_t)(i0 + r0) * NN;
    const int*   ar1  = adj + (size_t)(i0 + r1) * NN;

    uint4 nW[4];
    float nV = 0.f;
    int2  nA[8];

    // ---- prologue: stage tile 0, prefetch tile 1 (whf/vec) + tile 0 (adj) ----
#pragma unroll
    for (int i = 0; i < 4; i++) nW[i] = wf_g[t * 4 + i];
    if (t < 64)       nV = g_dst[t];
    else if (t < 128) nV = g_B[t - 64];
    else if (t < 192) nV = g_D[t - 128];
#pragma unroll
    for (int i = 0; i < 4; i++)
        reinterpret_cast<uint4*>(whf_s[0])[t * 4 + i] = nW[i];
    if (t < 64)       dst_s[0][t]      = nV;
    else if (t < 128) bf_s[0][t - 64]  = nV;
    else if (t < 192) df_s[0][t - 128] = nV;
#pragma unroll
    for (int i = 0; i < 4; i++) nW[i] = wf_g[1024 + t * 4 + i];
    if (t < 64)       nV = g_dst[BK + t];
    else if (t < 128) nV = g_B[BK + t - 64];
    else if (t < 192) nV = g_D[BK + t - 128];
#pragma unroll
    for (int q = 0; q < 2; q++) {
        int cq = sh * 32 + q * 16 + tig * 2;
        nA[q * 4 + 0] = *reinterpret_cast<const int2*>(ar0 + cq);
        nA[q * 4 + 1] = *reinterpret_cast<const int2*>(ar0 + cq + 8);
        nA[q * 4 + 2] = *reinterpret_cast<const int2*>(ar1 + cq);
        nA[q * 4 + 3] = *reinterpret_cast<const int2*>(ar1 + cq + 8);
    }
    __syncthreads();

    for (int jt = 0; jt < NJ; jt++) {
        const int buf = jt & 1;

        // consume adj prefetch; issue adj loads for tile jt+1
        int2 aq[8];
#pragma unroll
        for (int i = 0; i < 8; i++) aq[i] = nA[i];
        if (jt + 1 < NJ) {
            const int jn = (jt + 1) * BK;
#pragma unroll
            for (int q = 0; q < 2; q++) {
                int cq = jn + sh * 32 + q * 16 + tig * 2;
                nA[q * 4 + 0] = *reinterpret_cast<const int2*>(ar0 + cq);
                nA[q * 4 + 1] = *reinterpret_cast<const int2*>(ar0 + cq + 8);
                nA[q * 4 + 2] = *reinterpret_cast<const int2*>(ar1 + cq);
                nA[q * 4 + 3] = *reinterpret_cast<const int2*>(ar1 + cq + 8);
            }
        }

        // stage tile jt+1 into other buffer; prefetch tile jt+2
        if (jt + 1 < NJ) {
            const int nbuf = buf ^ 1;
#pragma unroll
            for (int i = 0; i < 4; i++)
                reinterpret_cast<uint4*>(whf_s[nbuf])[t * 4 + i] = nW[i];
            if (t < 64)       dst_s[nbuf][t]      = nV;
            else if (t < 128) bf_s[nbuf][t - 64]  = nV;
            else if (t < 192) df_s[nbuf][t - 128] = nV;
            if (jt + 2 < NJ) {
                const int jn2 = jt + 2;
#pragma unroll
                for (int i = 0; i < 4; i++)
                    nW[i] = wf_g[(size_t)jn2 * 1024 + t * 4 + i];
                const int j2 = jn2 * BK;
                if (t < 64)       nV = g_dst[j2 + t];
                else if (t < 128) nV = g_B[j2 + t - 64];
                else if (t < 192) nV = g_D[j2 + t - 128];
            }
        }

        // ---- compute this warp's 2 k16-steps ----
#pragma unroll
        for (int q = 0; q < 2; q++) {
            const int s   = sh * 2 + q;
            const int c01 = s * 16 + tig * 2;
            const int c23 = c01 + 8;
            float2 d0 = *reinterpret_cast<const float2*>(&dst_s[buf][c01]);
            float2 d1 = *reinterpret_cast<const float2*>(&dst_s[buf][c23]);
            float2 B0 = *reinterpret_cast<const float2*>(&bf_s[buf][c01]);
            float2 B1 = *reinterpret_cast<const float2*>(&bf_s[buf][c23]);
            float2 D0 = *reinterpret_cast<const float2*>(&df_s[buf][c01]);
            float2 D1 = *reinterpret_cast<const float2*>(&df_s[buf][c23]);
            int2 m00 = aq[q * 4 + 0];   // (r0, c01 pair)
            int2 m01 = aq[q * 4 + 1];   // (r0, c23 pair)
            int2 m10 = aq[q * 4 + 2];   // (r1, c01 pair)
            int2 m11 = aq[q * 4 + 3];   // (r1, c23 pair)

            float pa = (m00.x > 0) ? ((s0 + d0.x >= 0.f) ? A0 * B0.x : C0 * D0.x) : 0.f;
            float pb = (m00.y > 0) ? ((s0 + d0.y >= 0.f) ? A0 * B0.y : C0 * D0.y) : 0.f;
            float pc = (m10.x > 0) ? ((s1 + d0.x >= 0.f) ? A1 * B0.x : C1 * D0.x) : 0.f;
            float pd = (m10.y > 0) ? ((s1 + d0.y >= 0.f) ? A1 * B0.y : C1 * D0.y) : 0.f;
            float pe = (m01.x > 0) ? ((s0 + d1.x >= 0.f) ? A0 * B1.x : C0 * D1.x) : 0.f;
            float pf = (m01.y > 0) ? ((s0 + d1.y >= 0.f) ? A0 * B1.y : C0 * D1.y) : 0.f;
            float pg = (m11.x > 0) ? ((s1 + d1.x >= 0.f) ? A1 * B1.x : C1 * D1.x) : 0.f;
            float ph = (m11.y > 0) ? ((s1 + d1.y >= 0.f) ? A1 * B1.y : C1 * D1.y) : 0.f;

            uint32_t a0 = pack_bf16x2(pa, pb);
            uint32_t a1 = pack_bf16x2(pc, pd);
            uint32_t a2 = pack_bf16x2(pe, pf);
            uint32_t a3 = pack_bf16x2(pg, ph);

            if (wn == 0)
                mma16816(lacc, a0, a1, a2, a3, ones_b, ones_b);

#pragma unroll
            for (int nbp = 0; nbp < 4; nbp++) {
                uint4 b = *reinterpret_cast<const uint4*>(
                    &whf_s[buf][s * 1024 + (wn * 4 + nbp) * 128 + l * 4]);
                mma16816(acc[2 * nbp],     a0, a1, a2, a3, b.x, b.y);
                mma16816(acc[2 * nbp + 1], a0, a1, a2, a3, b.z, b.w);
            }
        }
        __syncthreads();
    }

    // ---- combine k-split halves ----
    const int pair = wm * 2 + wn;    // 0..3
    if (sh == 1) {
#pragma unroll
        for (int nb = 0; nb < 8; nb++)
            *reinterpret_cast<float4*>(&red_s[pair * 1024 + nb * 128 + l * 4]) =
                *reinterpret_cast<const float4*>(acc[nb]);
        if (wn == 0)
            *reinterpret_cast<float4*>(&l_red[wm * 128 + l * 4]) =
                *reinterpret_cast<const float4*>(lacc);
    }
    __syncthreads();
    if (sh == 0) {
#pragma unroll
        for (int nb = 0; nb < 8; nb++) {
            float4 v =
                *reinterpret_cast<const float4*>(&red_s[pair * 1024 + nb * 128 + l * 4]);
            acc[nb][0] += v.x; acc[nb][1] += v.y; acc[nb][2] += v.z; acc[nb][3] += v.w;
        }
        if (wn == 0) {
            float4 v = *reinterpret_cast<const float4*>(&l_red[wm * 128 + l * 4]);
            lacc[0] += v.x; lacc[2] += v.z;
            if (tig == 0) { l_s[r0] = lacc[0]; l_s[r1] = lacc[2]; }
        }
    }
    __syncthreads();

    if (sh == 0) {
        const float inv0 = 1.f / l_s[r0];
        const float inv1 = 1.f / l_s[r1];
#pragma unroll
        for (int nb = 0; nb < 8; nb++) {
            int n = wn * 64 + nb * 8 + tig * 2;
            *reinterpret_cast<float2*>(out + (size_t)(i0 + r0) * FOUT + n) =
                make_float2(acc[nb][0] * inv0, acc[nb][1] * inv0);
            *reinterpret_cast<float2*>(out + (size_t)(i0 + r1) * FOUT + n) =
                make_float2(acc[nb][2] * inv1, acc[nb][3] * inv1);
        }
    }
}

// ---------------------------------------------------------------------------
extern "C" void kernel_launch(void* const* d_in, const int* in_sizes, int n_in,
                              void* d_out, int out_size) {
    const float* h   = nullptr;
    const int*   adj = nullptr;
    const float* W   = nullptr;
    const float* a   = nullptr;
    for (int i = 0; i < n_in; i++) {
        switch (in_sizes[i]) {
            case NN * FIN:   h   = (const float*)d_in[i]; break;
            case NN * NN:    adj = (const int*)d_in[i];   break;
            case FIN * FOUT: W   = (const float*)d_in[i]; break;
            case 2 * FOUT:   a   = (const float*)d_in[i]; break;
            default: break;
        }
    }
    float* out = (float*)d_out;

    wh_kernel<<<NN / 64, 256>>>(h, W, a);
    dstmax_kernel<<<1, 256>>>();
    vec_kernel<<<NN / 256, 256>>>();
    attn_kernel<<<NN / BM, 256>>>(adj, out);
}

// round 10
// speedup vs baseline: 1.4152x; 1.4152x over previous
#include <cuda_runtime.h>
#include <cuda_bf16.h>
#include <cstdint>

#define NN    8192
#define FIN   256
#define FOUT  128
#define SLOPE 0.01f
#define BM    64             // rows per attn CTA
#define BK    64             // j-tile
#define NJ    (NN / BK)      // 128 tiles

// ---------------- device scratch ----------------
// Wh packed as m16n8k16 B-fragments, LDS.128-friendly:
// u32 idx = K16*1024 + ((wn*4 + nbp)*32 + lane)*4 + nbl*2 + sel
__device__ uint32_t g_WhF[NN * 64];
__device__ float g_src[NN], g_dst[NN];
__device__ float g_A[NN], g_C[NN];   // row factors: exp(s-m), exp(.01 s - m)
__device__ float g_B[NN], g_D[NN];   // col factors: exp(d),   exp(.01 d)
__device__ float g_dstmax;

__device__ __forceinline__ uint32_t pack_bf16x2(float lo, float hi) {
    __nv_bfloat162 h2 = __floats2bfloat162_rn(lo, hi);
    return *reinterpret_cast<uint32_t*>(&h2);
}
__device__ __forceinline__ void mma16816(float* d, uint32_t a0, uint32_t a1,
                                         uint32_t a2, uint32_t a3,
                                         uint32_t b0, uint32_t b1) {
    asm volatile(
        "mma.sync.aligned.m16n8k16.row.col.f32.bf16.bf16.f32 "
        "{%0,%1,%2,%3}, {%4,%5,%6,%7}, {%8,%9}, {%0,%1,%2,%3};"
        : "+f"(d[0]), "+f"(d[1]), "+f"(d[2]), "+f"(d[3])
        : "r"(a0), "r"(a1), "r"(a2), "r"(a3), "r"(b0), "r"(b1));
}
__device__ __forceinline__ void cp16(uint32_t s, const void* g) {
    asm volatile("cp.async.cg.shared.global [%0], [%1], 16;" :: "r"(s), "l"(g));
}
__device__ __forceinline__ void cp4(uint32_t s, const void* g) {
    asm volatile("cp.async.ca.shared.global [%0], [%1], 4;" :: "r"(s), "l"(g));
}
#define CP_COMMIT() asm volatile("cp.async.commit_group;" ::: "memory")
#define CP_WAIT0()  asm volatile("cp.async.wait_group 0;" ::: "memory")

// ---------------------------------------------------------------------------
// Kernel A: Wh = h @ W; emits g_WhF (fragment-packed bf16) + g_src/g_dst.
// ---------------------------------------------------------------------------
__global__ __launch_bounds__(256) void wh_kernel(const float* __restrict__ h,
                                                 const float* __restrict__ W,
                                                 const float* __restrict__ a) {
    __shared__ float h_s[64][33];
    __shared__ float W_s[32][FOUT];
    __shared__ float a_s[2 * FOUT];
    __shared__ uint32_t frag_s[4096];

    const int t  = threadIdx.x;
    const int i0 = blockIdx.x * 64;
    a_s[t] = a[t];

    float C[4][8];
#pragma unroll
    for (int r = 0; r < 4; r++)
#pragma unroll
        for (int c = 0; c < 8; c++) C[r][c] = 0.f;

    const int tr = t >> 4, tc = t & 15;

    for (int k0 = 0; k0 < FIN; k0 += 32) {
        {
            int row = t >> 2, colb = (t & 3) * 8;
            const float4* s4 =
                reinterpret_cast<const float4*>(h + (size_t)(i0 + row) * FIN + k0 + colb);
#pragma unroll
            for (int q = 0; q < 2; q++) {
                float4 v = s4[q];
                h_s[row][colb + 4 * q + 0] = v.x;
                h_s[row][colb + 4 * q + 1] = v.y;
                h_s[row][colb + 4 * q + 2] = v.z;
                h_s[row][colb + 4 * q + 3] = v.w;
            }
        }
        {
            int row = t >> 3, colb = (t & 7) * 16;
            const float4* s4 =
                reinterpret_cast<const float4*>(W + (size_t)(k0 + row) * FOUT + colb);
            float4* d4 = reinterpret_cast<float4*>(&W_s[row][colb]);
#pragma unroll
            for (int q = 0; q < 4; q++) d4[q] = s4[q];
        }
        __syncthreads();
#pragma unroll
        for (int kk = 0; kk < 32; kk++) {
            float av[4];
#pragma unroll
            for (int r = 0; r < 4; r++) av[r] = h_s[tr * 4 + r][kk];
            float4 b0 = *reinterpret_cast<const float4*>(&W_s[kk][tc * 8]);
            float4 b1 = *reinterpret_cast<const float4*>(&W_s[kk][tc * 8 + 4]);
            float bv[8] = {b0.x, b0.y, b0.z, b0.w, b1.x, b1.y, b1.z, b1.w};
#pragma unroll
            for (int r = 0; r < 4; r++)
#pragma unroll
                for (int c = 0; c < 8; c++) C[r][c] += av[r] * bv[c];
        }
        __syncthreads();
    }

    float sp[4], dp[4];
#pragma unroll
    for (int r = 0; r < 4; r++) { sp[r] = 0.f; dp[r] = 0.f; }
#pragma unroll
    for (int r = 0; r < 4; r++)
#pragma unroll
        for (int c = 0; c < 8; c++) {
            int col = tc * 8 + c;
            sp[r] += C[r][c] * a_s[col];
            dp[r] += C[r][c] * a_s[FOUT + col];
        }
#pragma unroll
    for (int off = 8; off >= 1; off >>= 1) {
#pragma unroll
        for (int r = 0; r < 4; r++) {
            sp[r] += __shfl_down_sync(0xffffffffu, sp[r], off, 16);
            dp[r] += __shfl_down_sync(0xffffffffu, dp[r], off, 16);
        }
    }
    if (tc == 0) {
#pragma unroll
        for (int r = 0; r < 4; r++) {
            g_src[i0 + tr * 4 + r] = sp[r];
            g_dst[i0 + tr * 4 + r] = dp[r];
        }
    }

    // pack into LDS.128-friendly B-fragment layout
    const int wnp = tc >> 3;
    const int nb  = tc & 7;
    const int nbp = nb >> 1, nbl = nb & 1;
#pragma unroll
    for (int q = 0; q < 2; q++) {
        int kk   = tr * 4 + 2 * q;
        int Kloc = kk >> 4;
        int klo  = kk & 15;
        int sel  = klo >> 3;
        int tig  = (klo >> 1) & 3;
#pragma unroll
        for (int c = 0; c < 8; c++) {
            uint32_t v    = pack_bf16x2(C[2 * q][c], C[2 * q + 1][c]);
            int      lane = c * 4 + tig;
            frag_s[Kloc * 1024 + ((wnp * 4 + nbp) * 32 + lane) * 4 + nbl * 2 + sel] = v;
        }
    }
    __syncthreads();
    {
        uint4*       dst = reinterpret_cast<uint4*>(g_WhF + (size_t)i0 * 64);
        const uint4* src = reinterpret_cast<const uint4*>(frag_s);
#pragma unroll
        for (int i = 0; i < 4; i++) dst[t * 4 + i] = src[t * 4 + i];
    }
}

// ---------------------------------------------------------------------------
__global__ __launch_bounds__(256) void dstmax_kernel() {
    __shared__ float red[256];
    int t = threadIdx.x;
    float m = -1e30f;
    for (int i = t; i < NN; i += 256) m = fmaxf(m, g_dst[i]);
    red[t] = m;
    __syncthreads();
    for (int s = 128; s > 0; s >>= 1) {
        if (t < s) red[t] = fmaxf(red[t], red[t + s]);
        __syncthreads();
    }
    if (t == 0) g_dstmax = red[0];
}

__global__ __launch_bounds__(256) void vec_kernel() {
    int   i = blockIdx.x * 256 + threadIdx.x;
    float s = g_src[i], d = g_dst[i];
    float x = s + g_dstmax;
    float m = x > 0.f ? x : SLOPE * x;
    g_A[i] = __expf(s - m);
    g_C[i] = __expf(SLOPE * s - m);
    g_B[i] = __expf(d);
    g_D[i] = __expf(SLOPE * d);
}

// ---------------------------------------------------------------------------
// Kernel D: fused masked softmax + (att @ Wh), bf16 HMMA.
// 128 CTAs x 512 thr (16 warps): wm=w&3 (16 rows), wn=(w>>2)&1 (64 cols),
// sh=w>>3 (2 of 4 k16-steps). cp.async double-buffered whf/vec staging ->
// ONE sync/tile; adj fragments straight from gmem one tile ahead.
// ---------------------------------------------------------------------------
__global__ __launch_bounds__(512, 1) void attn_kernel(const int* __restrict__ adj,
                                                      float* __restrict__ out) {
    __shared__ __align__(16) uint32_t whf_s[2][4096];   // 32 KB (reused for reduce)
    __shared__ __align__(16) float dst_s[2][64], bf_s[2][64], df_s[2][64];
    __shared__ __align__(16) float l_red[4 * 128];
    __shared__ float l_s[BM];

    float* red_s = reinterpret_cast<float*>(whf_s);

    const int t  = threadIdx.x;
    const int l  = t & 31;
    const int w  = t >> 5;
    const int wm = w & 3;
    const int wn = (w >> 2) & 1;
    const int sh = w >> 3;
    const int i0 = blockIdx.x * BM;

    const int r0  = wm * 16 + (l >> 2);
    const int r1  = r0 + 8;
    const int tig = l & 3;

    const float s0 = g_src[i0 + r0], A0 = g_A[i0 + r0], C0 = g_C[i0 + r0];
    const float s1 = g_src[i0 + r1], A1 = g_A[i0 + r1], C1 = g_C[i0 + r1];

    const uint32_t ones_b = (l < 4) ? 0x3F803F80u : 0u;

    float acc[8][4];
#pragma unroll
    for (int nb = 0; nb < 8; nb++)
#pragma unroll
        for (int q = 0; q < 4; q++) acc[nb][q] = 0.f;
    float lacc[4] = {0.f, 0.f, 0.f, 0.f};

    const uint4* wf_g = reinterpret_cast<const uint4*>(g_WhF);
    const int*   ar0  = adj + (size_t)(i0 + r0) * NN;
    const int*   ar1  = adj + (size_t)(i0 + r1) * NN;

    // staging smem byte-addresses for this thread (2x 16B whf + 1x 4B vec)
    const uint32_t whf_sa[2] = {
        (uint32_t)__cvta_generic_to_shared(&whf_s[0][t * 8]),
        (uint32_t)__cvta_generic_to_shared(&whf_s[1][t * 8])};
    uint32_t vec_sa[2] = {0, 0};
    const float* vec_g = nullptr;
    if (t < 64) {
        vec_sa[0] = (uint32_t)__cvta_generic_to_shared(&dst_s[0][t]);
        vec_sa[1] = (uint32_t)__cvta_generic_to_shared(&dst_s[1][t]);
        vec_g = g_dst + t;
    } else if (t < 128) {
        vec_sa[0] = (uint32_t)__cvta_generic_to_shared(&bf_s[0][t - 64]);
        vec_sa[1] = (uint32_t)__cvta_generic_to_shared(&bf_s[1][t - 64]);
        vec_g = g_B + (t - 64);
    } else if (t < 192) {
        vec_sa[0] = (uint32_t)__cvta_generic_to_shared(&df_s[0][t - 128]);
        vec_sa[1] = (uint32_t)__cvta_generic_to_shared(&df_s[1][t - 128]);
        vec_g = g_D + (t - 128);
    }

    // ---- prologue: async-stage tile 0; prefetch adj tile 0 into regs ----
    cp16(whf_sa[0], wf_g + t * 2);
    cp16(whf_sa[0] + 16, wf_g + t * 2 + 1);
    if (t < 192) cp4(vec_sa[0], vec_g);
    CP_COMMIT();

    int2 nA[8];
#pragma unroll
    for (int q = 0; q < 2; q++) {
        int cq = sh * 32 + q * 16 + tig * 2;
        nA[q * 4 + 0] = *reinterpret_cast<const int2*>(ar0 + cq);
        nA[q * 4 + 1] = *reinterpret_cast<const int2*>(ar0 + cq + 8);
        nA[q * 4 + 2] = *reinterpret_cast<const int2*>(ar1 + cq);
        nA[q * 4 + 3] = *reinterpret_cast<const int2*>(ar1 + cq + 8);
    }
    CP_WAIT0();
    __syncthreads();

    for (int jt = 0; jt < NJ; jt++) {
        const int buf = jt & 1;

        // async-stage tile jt+1 into the other buffer
        if (jt + 1 < NJ) {
            const uint4* wsrc = wf_g + (size_t)(jt + 1) * 1024 + t * 2;
            cp16(whf_sa[buf ^ 1], wsrc);
            cp16(whf_sa[buf ^ 1] + 16, wsrc + 1);
            if (t < 192) cp4(vec_sa[buf ^ 1], vec_g + (jt + 1) * BK);
            CP_COMMIT();
        }

        // consume adj prefetch; issue adj loads for tile jt+1
        int2 aq[8];
#pragma unroll
        for (int i = 0; i < 8; i++) aq[i] = nA[i];
        if (jt + 1 < NJ) {
            const int jn = (jt + 1) * BK;
#pragma unroll
            for (int q = 0; q < 2; q++) {
                int cq = jn + sh * 32 + q * 16 + tig * 2;
                nA[q * 4 + 0] = *reinterpret_cast<const int2*>(ar0 + cq);
                nA[q * 4 + 1] = *reinterpret_cast<const int2*>(ar0 + cq + 8);
                nA[q * 4 + 2] = *reinterpret_cast<const int2*>(ar1 + cq);
                nA[q * 4 + 3] = *reinterpret_cast<const int2*>(ar1 + cq + 8);
            }
        }

        // ---- compute this warp's 2 k16-steps from buf ----
#pragma unroll
        for (int q = 0; q < 2; q++) {
            const int s   = sh * 2 + q;
            const int c01 = s * 16 + tig * 2;
            const int c23 = c01 + 8;
            float2 d0 = *reinterpret_cast<const float2*>(&dst_s[buf][c01]);
            float2 d1 = *reinterpret_cast<const float2*>(&dst_s[buf][c23]);
            float2 B0 = *reinterpret_cast<const float2*>(&bf_s[buf][c01]);
            float2 B1 = *reinterpret_cast<const float2*>(&bf_s[buf][c23]);
            float2 D0 = *reinterpret_cast<const float2*>(&df_s[buf][c01]);
            float2 D1 = *reinterpret_cast<const float2*>(&df_s[buf][c23]);
            int2 m00 = aq[q * 4 + 0];
            int2 m01 = aq[q * 4 + 1];
            int2 m10 = aq[q * 4 + 2];
            int2 m11 = aq[q * 4 + 3];

            float pa = (m00.x > 0) ? ((s0 + d0.x >= 0.f) ? A0 * B0.x : C0 * D0.x) : 0.f;
            float pb = (m00.y > 0) ? ((s0 + d0.y >= 0.f) ? A0 * B0.y : C0 * D0.y) : 0.f;
            float pc = (m10.x > 0) ? ((s1 + d0.x >= 0.f) ? A1 * B0.x : C1 * D0.x) : 0.f;
            float pd = (m10.y > 0) ? ((s1 + d0.y >= 0.f) ? A1 * B0.y : C1 * D0.y) : 0.f;
            float pe = (m01.x > 0) ? ((s0 + d1.x >= 0.f) ? A0 * B1.x : C0 * D1.x) : 0.f;
            float pf = (m01.y > 0) ? ((s0 + d1.y >= 0.f) ? A0 * B1.y : C0 * D1.y) : 0.f;
            float pg = (m11.x > 0) ? ((s1 + d1.x >= 0.f) ? A1 * B1.x : C1 * D1.x) : 0.f;
            float ph = (m11.y > 0) ? ((s1 + d1.y >= 0.f) ? A1 * B1.y : C1 * D1.y) : 0.f;

            uint32_t a0 = pack_bf16x2(pa, pb);
            uint32_t a1 = pack_bf16x2(pc, pd);
            uint32_t a2 = pack_bf16x2(pe, pf);
            uint32_t a3 = pack_bf16x2(pg, ph);

            if (wn == 0)
                mma16816(lacc, a0, a1, a2, a3, ones_b, ones_b);

#pragma unroll
            for (int nbp = 0; nbp < 4; nbp++) {
                uint4 b = *reinterpret_cast<const uint4*>(
                    &whf_s[buf][s * 1024 + (wn * 4 + nbp) * 128 + l * 4]);
                mma16816(acc[2 * nbp],     a0, a1, a2, a3, b.x, b.y);
                mma16816(acc[2 * nbp + 1], a0, a1, a2, a3, b.z, b.w);
            }
        }

        CP_WAIT0();
        __syncthreads();
    }

    // ---- combine k-split halves (red_s aliases whf_s; compute all done) ----
    const int pair = wm * 2 + wn;    // 0..7
    if (sh == 1) {
#pragma unroll
        for (int nb = 0; nb < 8; nb++)
            *reinterpret_cast<float4*>(&red_s[pair * 1024 + nb * 128 + l * 4]) =
                *reinterpret_cast<const float4*>(acc[nb]);
        if (wn == 0)
            *reinterpret_cast<float4*>(&l_red[wm * 128 + l * 4]) =
                *reinterpret_cast<const float4*>(lacc);
    }
    __syncthreads();
    if (sh == 0) {
#pragma unroll
        for (int nb = 0; nb < 8; nb++) {
            float4 v =
                *reinterpret_cast<const float4*>(&red_s[pair * 1024 + nb * 128 + l * 4]);
            acc[nb][0] += v.x; acc[nb][1] += v.y; acc[nb][2] += v.z; acc[nb][3] += v.w;
        }
        if (wn == 0) {
            float4 v = *reinterpret_cast<const float4*>(&l_red[wm * 128 + l * 4]);
            lacc[0] += v.x; lacc[2] += v.z;
            if (tig == 0) { l_s[r0] = lacc[0]; l_s[r1] = lacc[2]; }
        }
    }
    __syncthreads();

    if (sh == 0) {
        const float inv0 = 1.f / l_s[r0];
        const float inv1 = 1.f / l_s[r1];
#pragma unroll
        for (int nb = 0; nb < 8; nb++) {
            int n = wn * 64 + nb * 8 + tig * 2;
            *reinterpret_cast<float2*>(out + (size_t)(i0 + r0) * FOUT + n) =
                make_float2(acc[nb][0] * inv0, acc[nb][1] * inv0);
            *reinterpret_cast<float2*>(out + (size_t)(i0 + r1) * FOUT + n) =
                make_float2(acc[nb][2] * inv1, acc[nb][3] * inv1);
        }
    }
}

// ---------------------------------------------------------------------------
extern "C" void kernel_launch(void* const* d_in, const int* in_sizes, int n_in,
                              void* d_out, int out_size) {
    const float* h   = nullptr;
    const int*   adj = nullptr;
    const float* W   = nullptr;
    const float* a   = nullptr;
    for (int i = 0; i < n_in; i++) {
        switch (in_sizes[i]) {
            case NN * FIN:   h   = (const float*)d_in[i]; break;
            case NN * NN:    adj = (const int*)d_in[i];   break;
            case FIN * FOUT: W   = (const float*)d_in[i]; break;
            case 2 * FOUT:   a   = (const float*)d_in[i]; break;
            default: break;
        }
    }
    float* out = (float*)d_out;

    wh_kernel<<<NN / 64, 256>>>(h, W, a);
    dstmax_kernel<<<1, 256>>>();
    vec_kernel<<<NN / 256, 256>>>();
    attn_kernel<<<NN / BM, 512>>>(adj, out);
}